// round 7
// baseline (speedup 1.0000x reference)
#include <cuda_runtime.h>
#include <cuda_bf16.h>
#include <cstdint>

// ---------------------------------------------------------------------------
// out = BN( sign(x) @ sign(W)^T ),  x[8192,2048], W[2048,2048] fp32.
// tcgen05 is unavailable (harness assembles for sm_103, not sm_103a), so:
// binarize -> int8 mma.sync GEMM (s32 accum, exact) -> column stats -> norm.
// ---------------------------------------------------------------------------

static constexpr int Mdim = 8192;
static constexpr int Ndim = 2048;
static constexpr int Kdim = 2048;

__device__ int8_t g_xa[(size_t)Mdim * Kdim];          // 16 MB
__device__ int8_t g_wa[(size_t)Ndim * Kdim];          //  4 MB
__device__ float  g_gemm[(size_t)Mdim * Ndim];        // 64 MB
__device__ float  g_psum[64 * Ndim];
__device__ float  g_psq [64 * Ndim];
__device__ float  g_scale[Ndim];
__device__ float  g_shift[Ndim];

// ---------------------------------------------------------------------------
// Helpers
// ---------------------------------------------------------------------------
__device__ __forceinline__ uint32_t smem_u32(const void* p) {
    uint32_t r;
    asm("{ .reg .u64 t; cvta.to.shared.u64 t, %1; cvt.u32.u64 %0, t; }"
        : "=r"(r) : "l"(p));
    return r;
}

__device__ __forceinline__ void cp16(uint32_t saddr, const void* gaddr) {
    asm volatile("cp.async.cg.shared.global [%0], [%1], 16;"
                 :: "r"(saddr), "l"(gaddr));
}

// SW64 swizzle for 64-byte rows: bits[5:4] ^= bits[8:7]
__device__ __forceinline__ uint32_t swz64(uint32_t off) {
    return off ^ ((off >> 3) & 0x30);
}

#define LDSM_X4(R0, R1, R2, R3, addr)                                        \
    asm volatile("ldmatrix.sync.aligned.m8n8.x4.shared.b16 {%0,%1,%2,%3}, [%4];" \
                 : "=r"(R0), "=r"(R1), "=r"(R2), "=r"(R3) : "r"(addr))

__device__ __forceinline__ void mma_s8(int& c0, int& c1, int& c2, int& c3,
                                       uint32_t a0, uint32_t a1, uint32_t a2,
                                       uint32_t a3, uint32_t b0, uint32_t b1) {
    asm volatile(
        "mma.sync.aligned.m16n8k32.row.col.s32.s8.s8.s32 "
        "{%0,%1,%2,%3}, {%4,%5,%6,%7}, {%8,%9}, {%0,%1,%2,%3};"
        : "+r"(c0), "+r"(c1), "+r"(c2), "+r"(c3)
        : "r"(a0), "r"(a1), "r"(a2), "r"(a3), "r"(b0), "r"(b1));
}

// ---------------------------------------------------------------------------
// Kernels 1/2: binarize fp32 -> int8 {-1, 0, +1}
// ---------------------------------------------------------------------------
__device__ __forceinline__ int8_t sgn8(float a) {
    return (int8_t)((a > 0.0f) ? 1 : ((a < 0.0f) ? -1 : 0));
}

__global__ void binx_kernel(const float4* __restrict__ in) {
    int i = blockIdx.x * blockDim.x + threadIdx.x;
    float4 v = in[i];
    char4 r = make_char4(sgn8(v.x), sgn8(v.y), sgn8(v.z), sgn8(v.w));
    reinterpret_cast<char4*>(g_xa)[i] = r;
}

__global__ void binw_kernel(const float4* __restrict__ in) {
    int i = blockIdx.x * blockDim.x + threadIdx.x;
    float4 v = in[i];
    char4 r = make_char4(sgn8(v.x), sgn8(v.y), sgn8(v.z), sgn8(v.w));
    reinterpret_cast<char4*>(g_wa)[i] = r;
}

// ---------------------------------------------------------------------------
// Kernel 3: int8 GEMM  D[8192,2048] = Xa @ Wa^T
// CTA tile 128x128, BK=64, 4-stage cp.async pipeline, 256 threads (2x4 warps),
// warp tile 64x32, mma.sync.m16n8k32.s8, SW64-swizzled smem + ldmatrix.x4.
// ---------------------------------------------------------------------------
static constexpr int BM = 128, BN = 128, BK = 64, STAGES = 4;
static constexpr int KTILES = Kdim / BK;                  // 32
static constexpr int A_BYTES = BM * BK;                   // 8 KB
static constexpr int B_BYTES = BN * BK;                   // 8 KB
static constexpr int STAGE_BYTES = A_BYTES + B_BYTES;     // 16 KB
static constexpr int GEMM_SMEM = STAGES * STAGE_BYTES;    // 64 KB

__global__ void __launch_bounds__(256)
gemm_kernel() {
    __shared__ __align__(1024) char smraw[GEMM_SMEM];

    const int tid  = threadIdx.x;
    const int lane = tid & 31;
    const int wid  = tid >> 5;
    const int warpM = wid >> 2;            // 0..1 -> 64 rows each
    const int warpN = wid & 3;             // 0..3 -> 32 cols each
    const int tileM = blockIdx.y;          // 0..63
    const int tileN = blockIdx.x;          // 0..15

    const uint32_t smBase = smem_u32(smraw);

    const int8_t* gA = g_xa + (size_t)tileM * BM * Kdim;
    const int8_t* gB = g_wa + (size_t)tileN * BN * Kdim;

    auto load_stage = [&](int s, int kt) {
        uint32_t aBase = smBase + (uint32_t)s * STAGE_BYTES;
        uint32_t bBase = aBase + A_BYTES;
        // A: 512 x 16B chunks, row = c>>2 (64B rows), seg = c&3
        #pragma unroll
        for (int i = 0; i < 2; i++) {
            int c = i * 256 + tid;
            int row = c >> 2, seg = c & 3;
            cp16(aBase + swz64((uint32_t)c * 16),
                 gA + (size_t)row * Kdim + kt * BK + seg * 16);
        }
        #pragma unroll
        for (int i = 0; i < 2; i++) {
            int c = i * 256 + tid;
            int row = c >> 2, seg = c & 3;
            cp16(bBase + swz64((uint32_t)c * 16),
                 gB + (size_t)row * Kdim + kt * BK + seg * 16);
        }
        asm volatile("cp.async.commit_group;" ::: "memory");
    };

    // ldmatrix per-lane addressing: lanes 0-7 tile0 rows, 8-15 tile1 rows,
    // 16-23 tile2 (rows 0-7, +16B), 24-31 tile3 (rows 8-15, +16B)
    const int lrow = (lane & 7) + (((lane >> 3) & 1) << 3);
    const int lkb  = ((lane >> 4) & 1) * 16;

    uint32_t aoff[4], boff[2];
    #pragma unroll
    for (int mi = 0; mi < 4; mi++)
        aoff[mi] = (uint32_t)(warpM * 64 + mi * 16 + lrow) * 64 + lkb;
    #pragma unroll
    for (int p = 0; p < 2; p++)
        boff[p] = (uint32_t)(warpN * 32 + p * 16 + lrow) * 64 + lkb;

    int acc[4][4][4];
    #pragma unroll
    for (int mi = 0; mi < 4; mi++)
        #pragma unroll
        for (int ni = 0; ni < 4; ni++)
            #pragma unroll
            for (int r = 0; r < 4; r++) acc[mi][ni][r] = 0;

    // prologue: stages 0..STAGES-2
    #pragma unroll
    for (int s = 0; s < STAGES - 1; s++) load_stage(s, s);

    for (int kt = 0; kt < KTILES; kt++) {
        const int s = kt & (STAGES - 1);
        asm volatile("cp.async.wait_group %0;" :: "n"(STAGES - 2) : "memory");
        __syncthreads();

        // issue next stage's loads before compute (overlap)
        const int nk = kt + STAGES - 1;
        if (nk < KTILES) {
            load_stage(nk & (STAGES - 1), nk);
        } else {
            asm volatile("cp.async.commit_group;" ::: "memory");
        }

        const uint32_t aBase = smBase + (uint32_t)s * STAGE_BYTES;
        const uint32_t bBase = aBase + A_BYTES;

        #pragma unroll
        for (int k32 = 0; k32 < 2; k32++) {
            uint32_t a[4][4], b[2][4];
            #pragma unroll
            for (int mi = 0; mi < 4; mi++) {
                LDSM_X4(a[mi][0], a[mi][1], a[mi][2], a[mi][3],
                        aBase + swz64(aoff[mi] + k32 * 32));
            }
            #pragma unroll
            for (int p = 0; p < 2; p++) {
                LDSM_X4(b[p][0], b[p][1], b[p][2], b[p][3],
                        bBase + swz64(boff[p] + k32 * 32));
            }
            #pragma unroll
            for (int mi = 0; mi < 4; mi++) {
                #pragma unroll
                for (int ni = 0; ni < 4; ni++) {
                    const int p = ni >> 1, sub = ni & 1;
                    mma_s8(acc[mi][ni][0], acc[mi][ni][1],
                           acc[mi][ni][2], acc[mi][ni][3],
                           a[mi][0], a[mi][1], a[mi][2], a[mi][3],
                           b[p][sub], b[p][2 + sub]);
                }
            }
        }
    }

    // Epilogue: convert s32 -> f32, write directly to gmem.
    // c0,c1: (row = mi*16 + lane>>2, cols 2*(lane&3), +1); c2,c3: row+8.
    float* outBase = g_gemm + (size_t)(tileM * BM + warpM * 64) * Ndim
                   + tileN * BN + warpN * 32;
    const int erow = lane >> 2;
    const int ecol = (lane & 3) * 2;
    #pragma unroll
    for (int mi = 0; mi < 4; mi++) {
        #pragma unroll
        for (int ni = 0; ni < 4; ni++) {
            float* p0 = outBase + (size_t)(mi * 16 + erow) * Ndim + ni * 8 + ecol;
            float2 v0 = make_float2((float)acc[mi][ni][0], (float)acc[mi][ni][1]);
            float2 v1 = make_float2((float)acc[mi][ni][2], (float)acc[mi][ni][3]);
            *reinterpret_cast<float2*>(p0) = v0;
            *reinterpret_cast<float2*>(p0 + (size_t)8 * Ndim) = v1;
        }
    }
}

// ---------------------------------------------------------------------------
// Kernel 4: deterministic partial column reductions (sum, sumsq)
// grid (16, 64): x -> 128-col block, y -> 128-row chunk
// ---------------------------------------------------------------------------
__global__ void reduce_kernel() {
    int col = blockIdx.x * 128 + threadIdx.x;
    int r0  = blockIdx.y * 128;
    const float* p = g_gemm + (size_t)r0 * Ndim + col;
    float s = 0.f, q = 0.f;
    #pragma unroll 4
    for (int r = 0; r < 128; r++) {
        float v = p[(size_t)r * Ndim];
        s += v;
        q += v * v;
    }
    g_psum[blockIdx.y * Ndim + col] = s;
    g_psq [blockIdx.y * Ndim + col] = q;
}

// ---------------------------------------------------------------------------
// Kernel 5: finalize stats -> per-column scale/shift
// ---------------------------------------------------------------------------
__global__ void finalize_kernel(const float* __restrict__ gamma,
                                const float* __restrict__ beta) {
    int c = blockIdx.x * blockDim.x + threadIdx.x;
    float s = 0.f, q = 0.f;
    #pragma unroll 8
    for (int i = 0; i < 64; i++) {
        s += g_psum[i * Ndim + c];
        q += g_psq [i * Ndim + c];
    }
    const float invB = 1.0f / (float)Mdim;
    float mean = s * invB;
    float var  = q * invB - mean * mean;
    float inv  = rsqrtf(var + 1e-5f);
    float sc   = gamma[c] * inv;
    g_scale[c] = sc;
    g_shift[c] = beta[c] - mean * sc;
}

// ---------------------------------------------------------------------------
// Kernel 6: normalize into d_out
// ---------------------------------------------------------------------------
__global__ void normalize_kernel(float4* __restrict__ out) {
    int i = blockIdx.x * blockDim.x + threadIdx.x;
    int c0 = (i * 4) & (Ndim - 1);
    float4 v = reinterpret_cast<const float4*>(g_gemm)[i];
    float4 o;
    o.x = v.x * g_scale[c0 + 0] + g_shift[c0 + 0];
    o.y = v.y * g_scale[c0 + 1] + g_shift[c0 + 1];
    o.z = v.z * g_scale[c0 + 2] + g_shift[c0 + 2];
    o.w = v.w * g_scale[c0 + 3] + g_shift[c0 + 3];
    out[i] = o;
}

// ---------------------------------------------------------------------------
// Launch
// ---------------------------------------------------------------------------
extern "C" void kernel_launch(void* const* d_in, const int* in_sizes, int n_in,
                              void* d_out, int out_size) {
    const float* x     = (const float*)d_in[0];
    const float* w     = (const float*)d_in[1];
    const float* gamma = (const float*)d_in[2];
    const float* beta  = (const float*)d_in[3];
    float* out = (float*)d_out;

    binx_kernel<<<(Mdim * Kdim / 4) / 256, 256>>>((const float4*)x);
    binw_kernel<<<(Ndim * Kdim / 4) / 256, 256>>>((const float4*)w);

    dim3 ggrid(Ndim / BN, Mdim / BM);   // (16, 64)
    gemm_kernel<<<ggrid, 256>>>();

    reduce_kernel<<<dim3(Ndim / 128, Mdim / 128), 128>>>();
    finalize_kernel<<<Ndim / 256, 256>>>(gamma, beta);
    normalize_kernel<<<(Mdim * Ndim / 4) / 256, 256>>>((float4*)out);
}